// round 15
// baseline (speedup 1.0000x reference)
#include <cuda_runtime.h>
#include <cuda_fp16.h>
#include <stdint.h>

#define N_MAX 100000
#define E_MAX 6400000
#define NBLK  148
#define NTHR  1024

// ---- scratch (device globals: no allocation allowed) ----
__device__ int      g_src[E_MAX];
__device__ int      g_dst[E_MAX];
__device__ unsigned g_deg[N_MAX];
__device__ float    g_dinv[N_MAX];
__device__ __half   g_val[N_MAX];   // per-node payload (fp16, 195KB)
__device__ float    g_agg[N_MAX];   // layer-1 aggregation (fp32 atomics)
__device__ int      g_is64;         // edge_index dtype flag (1 = int64)
__device__ unsigned g_bar_count = 0;
__device__ unsigned g_bar_gen   = 0;

// ---------------------------------------------------------------------------
// grid-wide barrier: all NBLK blocks are co-resident (1 block/SM via smem).
// ---------------------------------------------------------------------------
__device__ __forceinline__ void gridsync() {
    __syncthreads();
    if (threadIdx.x == 0) {
        __threadfence();                       // publish this block's writes
        unsigned gen = *(volatile unsigned*)&g_bar_gen;
        if (atomicAdd(&g_bar_count, 1u) == (unsigned)(gridDim.x - 1)) {
            g_bar_count = 0;
            __threadfence();
            atomicAdd(&g_bar_gen, 1u);         // release all
        } else {
            while (*(volatile unsigned*)&g_bar_gen == gen) { }
        }
        __threadfence();                       // acquire others' writes
    }
    __syncthreads();
}

// ---------------------------------------------------------------------------
// threefry2x32 — exact JAX schedule: 20 rounds = 5 blocks of 4
// ---------------------------------------------------------------------------
__host__ __device__ __forceinline__ void tf2x32(uint32_t k0, uint32_t k1,
                                                uint32_t x0, uint32_t x1,
                                                uint32_t &o0, uint32_t &o1) {
    const uint32_t ks2 = k0 ^ k1 ^ 0x1BD11BDAu;
#define TF_RND(R) { x0 += x1; x1 = (x1 << (R)) | (x1 >> (32 - (R))); x1 ^= x0; }
    x0 += k0; x1 += k1;
    TF_RND(13) TF_RND(15) TF_RND(26) TF_RND(6)
    x0 += k1;  x1 += ks2 + 1u;
    TF_RND(17) TF_RND(29) TF_RND(16) TF_RND(24)
    x0 += ks2; x1 += k0 + 2u;
    TF_RND(13) TF_RND(15) TF_RND(26) TF_RND(6)
    x0 += k0;  x1 += k1 + 3u;
    TF_RND(17) TF_RND(29) TF_RND(16) TF_RND(24)
    x0 += k1;  x1 += ks2 + 4u;
    TF_RND(13) TF_RND(15) TF_RND(26) TF_RND(6)
    x0 += ks2; x1 += k0 + 5u;
#undef TF_RND
    o0 = x0; o1 = x1;
}

__device__ __forceinline__ bool keep_bit(uint32_t ka, uint32_t kb, uint32_t idx) {
    uint32_t a, b;
    tf2x32(ka, kb, 0u, idx, a, b);
    uint32_t bits = a ^ b;
    float u = __uint_as_float((bits >> 9) | 0x3f800000u) - 1.0f;
    return u < 0.4f;
}

// ---------------------------------------------------------------------------
// edge scatter loop (shared by both passes): agg[dst] += s_val[src],
// zero contributions skipped; streaming pipelined index loads.
// ---------------------------------------------------------------------------
__device__ __forceinline__ void edge_pass(const __half* s_val,
                                          float* __restrict__ agg, int n4) {
    const int4* s4 = reinterpret_cast<const int4*>(g_src);
    const int4* d4 = reinterpret_cast<const int4*>(g_dst);
    int stride = gridDim.x * blockDim.x;
    int i = blockIdx.x * blockDim.x + threadIdx.x;
    int4 s, d;
    bool valid = (i < n4);
    if (valid) { s = __ldcs(&s4[i]); d = __ldcs(&d4[i]); }
    while (valid) {
        int ni = i + stride;
        bool nvalid = (ni < n4);
        int4 ns, nd;
        if (nvalid) { ns = __ldcs(&s4[ni]); nd = __ldcs(&d4[ni]); }
        float v0 = __half2float(s_val[s.x]);
        float v1 = __half2float(s_val[s.y]);
        float v2 = __half2float(s_val[s.z]);
        float v3 = __half2float(s_val[s.w]);
        if (v0 != 0.0f) atomicAdd(&agg[d.x], v0);
        if (v1 != 0.0f) atomicAdd(&agg[d.y], v1);
        if (v2 != 0.0f) atomicAdd(&agg[d.z], v2);
        if (v3 != 0.0f) atomicAdd(&agg[d.w], v3);
        i = ni; s = ns; d = nd; valid = nvalid;
    }
}

__device__ __forceinline__ void stage_table(__half* s_val, int N) {
    int n_u4 = (N + 7) / 8;   // uint4 = 8 halves
    const uint4* st = reinterpret_cast<const uint4*>(g_val);
    uint4* dt = reinterpret_cast<uint4*>(s_val);
    for (int j = threadIdx.x; j < n_u4; j += blockDim.x)
        dt[j] = st[j];
    __syncthreads();
}

// ---------------------------------------------------------------------------
// one persistent kernel: all phases, grid barriers between
// ---------------------------------------------------------------------------
__global__ void __launch_bounds__(NTHR, 1)
k_fused(const float* __restrict__ x, const long long* __restrict__ e,
        const float* __restrict__ W1, const float* __restrict__ b1,
        const float* __restrict__ W2, const float* __restrict__ b2,
        float* __restrict__ out, int N, int E,
        uint32_t k1a, uint32_t k1b, uint32_t k2a, uint32_t k2b) {
    extern __shared__ __half s_val[];
    int gtid = blockIdx.x * blockDim.x + threadIdx.x;
    int gsz  = gridDim.x * blockDim.x;

    // ---- phase 0: zero deg/agg/out + dtype detect ----
    for (int n = gtid; n < N; n += gsz) {
        g_deg[n] = 0u; g_agg[n] = 0.0f; out[n] = 0.0f;
    }
    if (blockIdx.x == 0) {
        if (threadIdx.x == 0) g_is64 = 1;
        __syncthreads();
        const unsigned* eu = (const unsigned*)e;
        for (int j = threadIdx.x; j < 4096; j += blockDim.x)
            if (eu[2 * j + 1] != 0u) { atomicAnd(&g_is64, 0); break; }
    }
    gridsync();

    // ---- phase 1: convert edge_index -> int32 + degree count ----
    {
        int is64 = g_is64;
        int e4 = E / 4;
        for (int i = gtid; i < e4; i += gsz) {
            int4 sv, dv;
            if (is64) {
                const longlong2* s2 = reinterpret_cast<const longlong2*>(e);
                const longlong2* d2 = reinterpret_cast<const longlong2*>(e + E);
                longlong2 sa = s2[2 * i], sb = s2[2 * i + 1];
                longlong2 da = d2[2 * i], db = d2[2 * i + 1];
                sv = make_int4((int)sa.x, (int)sa.y, (int)sb.x, (int)sb.y);
                dv = make_int4((int)da.x, (int)da.y, (int)db.x, (int)db.y);
            } else {
                const int* e32 = reinterpret_cast<const int*>(e);
                sv = reinterpret_cast<const int4*>(e32)[i];
                dv = reinterpret_cast<const int4*>(e32 + E)[i];
            }
            reinterpret_cast<int4*>(g_src)[i] = sv;
            reinterpret_cast<int4*>(g_dst)[i] = dv;
            atomicAdd(&g_deg[dv.x], 1u);
            atomicAdd(&g_deg[dv.y], 1u);
            atomicAdd(&g_deg[dv.z], 1u);
            atomicAdd(&g_deg[dv.w], 1u);
        }
        int tail0 = e4 * 4;
        for (int j = tail0 + gtid; j < E; j += gsz) {
            int s, d;
            if (is64) { s = (int)e[j]; d = (int)e[E + j]; }
            else {
                const int* e32 = reinterpret_cast<const int*>(e);
                s = e32[j]; d = e32[E + j];
            }
            g_src[j] = s; g_dst[j] = d;
            atomicAdd(&g_deg[d], 1u);
        }
    }
    gridsync();

    // ---- phase 2: node1 — dinv, dropout1, val1 = h1*dinv ----
    for (int n = gtid; n < N; n += gsz) {
        unsigned dg = g_deg[n];
        float dinv = dg ? rsqrtf((float)dg) : 0.0f;
        g_dinv[n] = dinv;
        float h = keep_bit(k1a, k1b, (uint32_t)n) ? x[n] * 2.5f : 0.0f;
        g_val[n] = __float2half_rn(h * dinv);
    }
    gridsync();

    // ---- phase 3: edge pass 1 -> g_agg ----
    stage_table(s_val, N);
    edge_pass(s_val, g_agg, E / 4);
    gridsync();

    // ---- phase 4: node2 — relu+dropout2, dot W2, val2 = t*dinv ----
    for (int n = gtid; n < N; n += gsz) {
        float dinv = g_dinv[n];
        float s1 = g_agg[n] * dinv;
        uint32_t base = (uint32_t)n * 16u;
        float t = 0.0f;
#pragma unroll
        for (int c = 0; c < 16; c++) {
            float v = fmaxf(fmaf(s1, __ldg(&W1[c]), __ldg(&b1[c])), 0.0f);
            if (keep_bit(k2a, k2b, base + (uint32_t)c))
                t = fmaf(v * 2.5f, __ldg(&W2[c]), t);
        }
        g_val[n] = __float2half_rn(t * dinv);
    }
    gridsync();

    // ---- phase 5: edge pass 2 -> out ----
    stage_table(s_val, N);
    edge_pass(s_val, out, E / 4);
    gridsync();

    // ---- phase 6: final scale + bias ----
    float bb = __ldg(&b2[0]);
    for (int n = gtid; n < N; n += gsz)
        out[n] = out[n] * g_dinv[n] + bb;
}

// ---------------------------------------------------------------------------
// launch
// ---------------------------------------------------------------------------
extern "C" void kernel_launch(void* const* d_in, const int* in_sizes, int n_in,
                              void* d_out, int out_size) {
    const float*     x  = (const float*)d_in[0];
    const long long* ei = (const long long*)d_in[1];
    const float*     W1 = (const float*)d_in[2];
    const float*     b1 = (const float*)d_in[3];
    const float*     W2 = (const float*)d_in[4];
    const float*     b2 = (const float*)d_in[5];
    float* out = (float*)d_out;

    int N = in_sizes[0];
    int E = in_sizes[1] / 2;

    // JAX: key(42)=(0,42); partitionable split: subkey i = threefry(key,(0,i))
    uint32_t k1a, k1b, k2a, k2b;
    tf2x32(0u, 42u, 0u, 0u, k1a, k1b);
    tf2x32(0u, 42u, 0u, 1u, k2a, k2b);

    size_t smem_bytes = (((size_t)N * sizeof(__half)) + 15) & ~(size_t)15;
    cudaFuncSetAttribute(k_fused, cudaFuncAttributeMaxDynamicSharedMemorySize,
                         (int)smem_bytes);

    k_fused<<<NBLK, NTHR, smem_bytes>>>(x, ei, W1, b1, W2, b2, out, N, E,
                                        k1a, k1b, k2a, k2b);
}